// round 12
// baseline (speedup 1.0000x reference)
#include <cuda_runtime.h>
#include <cuda_bf16.h>
#include <cstdint>

// ---------------------------------------------------------------------------
// GCN: 4 layers, N=100000, E=1600000, 128->128->128->128->64
//   - k_wconv: one-time W -> packed bf16 hi/lo fragment planes (gmem)
//   - per layer: split-bf16 mma.sync GEMM, fused-pass mainloop:
//       per k-step load A(hi,lo) via ldmatrix + B(hi,lo) frags once,
//       issue all 3 split combos (Ahi*Bhi + Ahi*Blo + Alo*Bhi) -> 24 HMMA
//     then warp-per-node CSR aggregation (fused bias+relu)
//   - gemm1 at launch slot #4 for ncu capture
// ---------------------------------------------------------------------------

#define N_NODES 100000
#define N_EDGES 1600000
#define DIM 128

// ----------------------------- scratch --------------------------------------
__device__ float g_deg[N_NODES];
__device__ float g_dinv[N_NODES];
__device__ float g_self[N_NODES];
__device__ int   g_counts[N_NODES];
__device__ int   g_offsets[N_NODES + 1];
__device__ int   g_cursor[N_NODES];
__device__ int   g_blocksums[256];
__device__ int2  g_edges[N_EDGES];
__device__ float g_bufA[(size_t)N_NODES * DIM];
__device__ float g_bufB[(size_t)N_NODES * DIM];
// packed W planes: [matrix][plane(hi=0,lo=1)][(k/2)*WN + n]
__device__ uint32_t g_w128p[3][2][64 * 136];
__device__ uint32_t g_w64p[2][64 * 72];

// ----------------------------- preprocessing --------------------------------
__global__ void k_init_nodes() {
    int i = blockIdx.x * blockDim.x + threadIdx.x;
    if (i < N_NODES) {
        g_deg[i]    = 1.0f;
        g_counts[i] = 0;
        g_cursor[i] = 0;
    }
}

__global__ void k_edge_degree(const int* __restrict__ ei, const float* __restrict__ w) {
    int e = blockIdx.x * blockDim.x + threadIdx.x;
    if (e < N_EDGES) {
        int dst = ei[N_EDGES + e];
        atomicAdd(&g_deg[dst], w[e]);
        atomicAdd(&g_counts[dst], 1);
    }
}

#define SCAN_BS 1024
// scanA with fused dinv/self computation (same index domain)
__global__ void k_scanA() {
    __shared__ int s[SCAN_BS];
    int t = threadIdx.x;
    int i = blockIdx.x * SCAN_BS + t;
    if (i < N_NODES) {
        float d = g_deg[i];
        float r = (d > 0.0f) ? rsqrtf(d) : 0.0f;
        g_dinv[i] = r;
        g_self[i] = r * r;
    }
    int v = (i < N_NODES) ? g_counts[i] : 0;
    s[t] = v;
    __syncthreads();
    for (int off = 1; off < SCAN_BS; off <<= 1) {
        int x = (t >= off) ? s[t - off] : 0;
        __syncthreads();
        s[t] += x;
        __syncthreads();
    }
    if (i < N_NODES) g_offsets[i + 1] = s[t];
    if (t == SCAN_BS - 1) g_blocksums[blockIdx.x] = s[t];
}

__global__ void k_scanB(int nblocks) {
    if (threadIdx.x == 0 && blockIdx.x == 0) {
        int run = 0;
        for (int b = 0; b < nblocks; b++) {
            int v = g_blocksums[b];
            g_blocksums[b] = run;
            run += v;
        }
    }
}

__global__ void k_scanC() {
    int t = threadIdx.x;
    int i = blockIdx.x * SCAN_BS + t;
    if (i < N_NODES) g_offsets[i + 1] += g_blocksums[blockIdx.x];
    if (i == 0) g_offsets[0] = 0;
}

__global__ void k_place(const int* __restrict__ ei, const float* __restrict__ w) {
    int e = blockIdx.x * blockDim.x + threadIdx.x;
    if (e < N_EDGES) {
        int src = ei[e];
        int dst = ei[N_EDGES + e];
        int pos = g_offsets[dst] + atomicAdd(&g_cursor[dst], 1);
        float nm = g_dinv[src] * w[e] * g_dinv[dst];
        g_edges[pos] = make_int2(src, __float_as_int(nm));
    }
}

// ----------------------------- one-time W conversion -------------------------
__global__ void k_wconv(const float* __restrict__ W1, const float* __restrict__ W2,
                        const float* __restrict__ W3, const float* __restrict__ W4) {
    int m = blockIdx.x;
    const float* W = (m == 0) ? W1 : (m == 1) ? W2 : (m == 2) ? W3 : W4;
    int dout = (m < 3) ? 128 : 64;
    int wn   = (m < 3) ? 136 : 72;
    uint32_t* hi = (m < 3) ? g_w128p[m][0] : g_w64p[0];
    uint32_t* lo = (m < 3) ? g_w128p[m][1] : g_w64p[1];
    int total = 128 * dout;
    for (int e = threadIdx.x; e < total; e += blockDim.x) {
        int k = e / dout, n = e % dout;
        float v = W[(size_t)k * dout + n];
        __nv_bfloat16 h = __float2bfloat16_rn(v);
        __nv_bfloat16 l = __float2bfloat16_rn(v - __bfloat162float(h));
        int word = (k >> 1) * wn + n;
        int sel  = k & 1;
        reinterpret_cast<uint16_t*>(&hi[word])[sel] = *reinterpret_cast<uint16_t*>(&h);
        reinterpret_cast<uint16_t*>(&lo[word])[sel] = *reinterpret_cast<uint16_t*>(&l);
    }
}

// ----------------------------- split-bf16 mma.sync GEMM ---------------------
__device__ __forceinline__ void mma16816(float* c, const uint32_t* a,
                                         uint32_t b0, uint32_t b1) {
    asm volatile(
        "mma.sync.aligned.m16n8k16.row.col.f32.bf16.bf16.f32 "
        "{%0,%1,%2,%3}, {%4,%5,%6,%7}, {%8,%9}, {%0,%1,%2,%3};\n"
        : "+f"(c[0]), "+f"(c[1]), "+f"(c[2]), "+f"(c[3])
        : "r"(a[0]), "r"(a[1]), "r"(a[2]), "r"(a[3]), "r"(b0), "r"(b1));
}

__device__ __forceinline__ void ldmat_x4(uint32_t* r, uint32_t saddr) {
    asm volatile(
        "ldmatrix.sync.aligned.m8n8.x4.shared.b16 {%0,%1,%2,%3}, [%4];"
        : "=r"(r[0]), "=r"(r[1]), "=r"(r[2]), "=r"(r[3]) : "r"(saddr));
}

__device__ __forceinline__ uint32_t smem_u32(const void* p) {
    return (uint32_t)__cvta_generic_to_shared(p);
}

// out[64 x DOUT] per CTA = X[64,128] @ W[128,DOUT], fp32 in/out.
// X smem: bf16 [64][XP=136 halfwords] hi+lo planes (ldmatrix source).
// W smem: packed frag words uint32[(k/2)][WN] hi+lo planes.
// Warp (of 8): rg=w&1 -> rows rg*32 + [0..31] (2 m-blocks),
//              cg=w>>1 -> cols cg*(DOUT/4) (NT=DOUT/32 n-tiles).
template <int DOUT>
__global__ void __launch_bounds__(256, 2) k_gemm_mma(const float* __restrict__ X,
                                                     const uint32_t* __restrict__ WHIg,
                                                     const uint32_t* __restrict__ WLOg,
                                                     float* __restrict__ out) {
    constexpr int XP = 136;                       // halfwords per X row
    constexpr int WN = (DOUT == 128) ? 136 : 72;  // words per k-pair row
    constexpr int NT = DOUT / 32;                 // n-tiles per warp (4 / 2)
    constexpr int X_BYTES = 64 * XP * 2;          // 17408
    constexpr int W_WORDS = 64 * WN;              // 8704 / 4608

    extern __shared__ __align__(16) char smem[];
    uint16_t* XHI = reinterpret_cast<uint16_t*>(smem);
    uint16_t* XLO = reinterpret_cast<uint16_t*>(smem + X_BYTES);
    uint32_t* WHI = reinterpret_cast<uint32_t*>(smem + 2 * X_BYTES);
    uint32_t* WLO = WHI + W_WORDS;

    const int tid  = threadIdx.x;
    const int warp = tid >> 5;
    const int lane = tid & 31;
    const int g    = lane >> 2;
    const int tg   = lane & 3;
    const int row0 = blockIdx.x * 64;

    // ---- stage W planes (uint4 copy from packed gmem) ----------------------
    {
        constexpr int NV4 = W_WORDS / 4;
        uint4* dh = reinterpret_cast<uint4*>(WHI);
        uint4* dl = reinterpret_cast<uint4*>(WLO);
        const uint4* sh = reinterpret_cast<const uint4*>(WHIg);
        const uint4* sl = reinterpret_cast<const uint4*>(WLOg);
        for (int i = tid; i < NV4; i += 256) { dh[i] = sh[i]; dl[i] = sl[i]; }
    }

    // ---- stage X: fp32 -> bf16 hi/lo [row][k] ------------------------------
    {
#pragma unroll
        for (int i = 0; i < 8; i++) {
            int s   = tid + i * 256;              // 0..2047 float4s
            int r   = s >> 5;                     // row 0..63
            int k4  = (s & 31) * 4;
            int grow = row0 + r;
            float4 v = make_float4(0.f, 0.f, 0.f, 0.f);
            if (grow < N_NODES)
                v = *reinterpret_cast<const float4*>(&X[(size_t)grow * DIM + k4]);
            __nv_bfloat162 h0 = __floats2bfloat162_rn(v.x, v.y);
            __nv_bfloat162 h1 = __floats2bfloat162_rn(v.z, v.w);
            __nv_bfloat162 l0 = __floats2bfloat162_rn(v.x - __low2float(h0),
                                                      v.y - __high2float(h0));
            __nv_bfloat162 l1 = __floats2bfloat162_rn(v.z - __low2float(h1),
                                                      v.w - __high2float(h1));
            int hw = r * XP + k4;
            *reinterpret_cast<uint32_t*>(&XHI[hw])     = *reinterpret_cast<uint32_t*>(&h0);
            *reinterpret_cast<uint32_t*>(&XHI[hw + 2]) = *reinterpret_cast<uint32_t*>(&h1);
            *reinterpret_cast<uint32_t*>(&XLO[hw])     = *reinterpret_cast<uint32_t*>(&l0);
            *reinterpret_cast<uint32_t*>(&XLO[hw + 2]) = *reinterpret_cast<uint32_t*>(&l1);
        }
    }
    __syncthreads();

    // ---- warp geometry -----------------------------------------------------
    const int rg = warp & 1;                      // row group: rows rg*32..+31
    const int cg = warp >> 1;                     // col group: cols cg*(DOUT/4)
    const int nbase = cg * (NT * 8);

    // ldmatrix per-thread source offsets (bytes) at kb=0, for mb=0 and mb=1
    const int li  = lane & 7;
    const int grp = lane >> 3;
    const uint32_t aoff0 =
        ((uint32_t)(rg * 32 + li + (grp & 1) * 8) * XP + (grp >> 1) * 8) * 2;
    const uint32_t aoff1 = aoff0 + 16 * XP * 2;

    const uint32_t xhi_s = smem_u32(XHI);
    const uint32_t xlo_s = smem_u32(XLO);

    float acc[2][NT][4];
#pragma unroll
    for (int mb = 0; mb < 2; mb++)
#pragma unroll
        for (int nt = 0; nt < NT; nt++)
#pragma unroll
            for (int c = 0; c < 4; c++) acc[mb][nt][c] = 0.0f;

    // ---- fused-pass mainloop: per k-step, load A/B frags once, 24 HMMA -----
#pragma unroll
    for (int ks = 0; ks < 8; ks++) {
        uint32_t ah0[4], ah1[4], al0[4], al1[4];
        ldmat_x4(ah0, xhi_s + aoff0 + ks * 32);   // kb*2 bytes = ks*16*2
        ldmat_x4(ah1, xhi_s + aoff1 + ks * 32);
        ldmat_x4(al0, xlo_s + aoff0 + ks * 32);
        ldmat_x4(al1, xlo_s + aoff1 + ks * 32);
        const int kp = ks * 8 + tg;
#pragma unroll
        for (int nt = 0; nt < NT; nt++) {
            int n = nbase + nt * 8 + g;
            uint32_t bh0 = WHI[kp * WN + n];
            uint32_t bh1 = WHI[(kp + 4) * WN + n];
            uint32_t bl0 = WLO[kp * WN + n];
            uint32_t bl1 = WLO[(kp + 4) * WN + n];
            mma16816(acc[0][nt], ah0, bh0, bh1);   // Ahi * Bhi
            mma16816(acc[1][nt], ah1, bh0, bh1);
            mma16816(acc[0][nt], ah0, bl0, bl1);   // Ahi * Blo
            mma16816(acc[1][nt], ah1, bl0, bl1);
            mma16816(acc[0][nt], al0, bh0, bh1);   // Alo * Bhi
            mma16816(acc[1][nt], al1, bh0, bh1);
        }
    }

    // ---- epilogue: fragment stores straight to gmem ------------------------
#pragma unroll
    for (int mb = 0; mb < 2; mb++) {
        int r0g = row0 + rg * 32 + mb * 16 + g;
#pragma unroll
        for (int nt = 0; nt < NT; nt++) {
            int col = nbase + nt * 8 + tg * 2;
            if (r0g < N_NODES)
                *reinterpret_cast<float2*>(&out[(size_t)r0g * DOUT + col]) =
                    make_float2(acc[mb][nt][0], acc[mb][nt][1]);
            if (r0g + 8 < N_NODES)
                *reinterpret_cast<float2*>(&out[(size_t)(r0g + 8) * DOUT + col]) =
                    make_float2(acc[mb][nt][2], acc[mb][nt][3]);
        }
    }
}

// ----------------------------- aggregation: warp per node -------------------
template <int DOUT, bool RELU>
__global__ void __launch_bounds__(256) k_agg(const float* __restrict__ H,
                                             const float* __restrict__ bias,
                                             float* __restrict__ out) {
    int node = (blockIdx.x * blockDim.x + threadIdx.x) >> 5;
    int lane = threadIdx.x & 31;
    if (node >= N_NODES) return;

    constexpr int V = DOUT / 32;

    float acc[V];
    float s = g_self[node];
    if constexpr (V == 4) {
        float4 h = *reinterpret_cast<const float4*>(&H[(size_t)node * DOUT + lane * 4]);
        acc[0] = s * h.x; acc[1] = s * h.y; acc[2] = s * h.z; acc[3] = s * h.w;
    } else {
        float2 h = *reinterpret_cast<const float2*>(&H[(size_t)node * DOUT + lane * 2]);
        acc[0] = s * h.x; acc[1] = s * h.y;
    }

    const int2* __restrict__ ep = g_edges;
    int beg = g_offsets[node];
    int end = g_offsets[node + 1];

    int j = beg;
    for (; j + 4 <= end; j += 4) {
        int2 e0 = ep[j], e1 = ep[j + 1], e2 = ep[j + 2], e3 = ep[j + 3];
        float n0 = __int_as_float(e0.y), n1 = __int_as_float(e1.y);
        float n2 = __int_as_float(e2.y), n3 = __int_as_float(e3.y);
        if constexpr (V == 4) {
            float4 h0 = *reinterpret_cast<const float4*>(&H[(size_t)e0.x * DOUT + lane * 4]);
            float4 h1 = *reinterpret_cast<const float4*>(&H[(size_t)e1.x * DOUT + lane * 4]);
            float4 h2 = *reinterpret_cast<const float4*>(&H[(size_t)e2.x * DOUT + lane * 4]);
            float4 h3 = *reinterpret_cast<const float4*>(&H[(size_t)e3.x * DOUT + lane * 4]);
            acc[0] += n0 * h0.x; acc[1] += n0 * h0.y; acc[2] += n0 * h0.z; acc[3] += n0 * h0.w;
            acc[0] += n1 * h1.x; acc[1] += n1 * h1.y; acc[2] += n1 * h1.z; acc[3] += n1 * h1.w;
            acc[0] += n2 * h2.x; acc[1] += n2 * h2.y; acc[2] += n2 * h2.z; acc[3] += n2 * h2.w;
            acc[0] += n3 * h3.x; acc[1] += n3 * h3.y; acc[2] += n3 * h3.z; acc[3] += n3 * h3.w;
        } else {
            float2 h0 = *reinterpret_cast<const float2*>(&H[(size_t)e0.x * DOUT + lane * 2]);
            float2 h1 = *reinterpret_cast<const float2*>(&H[(size_t)e1.x * DOUT + lane * 2]);
            float2 h2 = *reinterpret_cast<const float2*>(&H[(size_t)e2.x * DOUT + lane * 2]);
            float2 h3 = *reinterpret_cast<const float2*>(&H[(size_t)e3.x * DOUT + lane * 2]);
            acc[0] += n0 * h0.x; acc[1] += n0 * h0.y;
            acc[0] += n1 * h1.x; acc[1] += n1 * h1.y;
            acc[0] += n2 * h2.x; acc[1] += n2 * h2.y;
            acc[0] += n3 * h3.x; acc[1] += n3 * h3.y;
        }
    }
    for (; j < end; j++) {
        int2 e = ep[j];
        float nm = __int_as_float(e.y);
        if constexpr (V == 4) {
            float4 h = *reinterpret_cast<const float4*>(&H[(size_t)e.x * DOUT + lane * 4]);
            acc[0] += nm * h.x; acc[1] += nm * h.y; acc[2] += nm * h.z; acc[3] += nm * h.w;
        } else {
            float2 h = *reinterpret_cast<const float2*>(&H[(size_t)e.x * DOUT + lane * 2]);
            acc[0] += nm * h.x; acc[1] += nm * h.y;
        }
    }

    if constexpr (V == 4) {
        float4 b = *reinterpret_cast<const float4*>(&bias[lane * 4]);
        acc[0] += b.x; acc[1] += b.y; acc[2] += b.z; acc[3] += b.w;
        if (RELU) {
#pragma unroll
            for (int c = 0; c < 4; c++) acc[c] = fmaxf(acc[c], 0.0f);
        }
        *reinterpret_cast<float4*>(&out[(size_t)node * DOUT + lane * 4]) =
            make_float4(acc[0], acc[1], acc[2], acc[3]);
    } else {
        float2 b = *reinterpret_cast<const float2*>(&bias[lane * 2]);
        acc[0] += b.x; acc[1] += b.y;
        if (RELU) {
            acc[0] = fmaxf(acc[0], 0.0f);
            acc[1] = fmaxf(acc[1], 0.0f);
        }
        *reinterpret_cast<float2*>(&out[(size_t)node * DOUT + lane * 2]) =
            make_float2(acc[0], acc[1]);
    }
}

// ----------------------------- launch ---------------------------------------
extern "C" void kernel_launch(void* const* d_in, const int* in_sizes, int n_in,
                              void* d_out, int out_size) {
    const float* x  = (const float*)d_in[0];
    const float* ew = (const float*)d_in[1];
    const int*   ei = (const int*)d_in[2];
    const float* W1 = (const float*)d_in[3];
    const float* b1 = (const float*)d_in[4];
    const float* W2 = (const float*)d_in[5];
    const float* b2 = (const float*)d_in[6];
    const float* W3 = (const float*)d_in[7];
    const float* b3 = (const float*)d_in[8];
    const float* W4 = (const float*)d_in[9];
    const float* b4 = (const float*)d_in[10];
    float* out = (float*)d_out;

    float *bufA, *bufB;
    cudaGetSymbolAddress((void**)&bufA, g_bufA);
    cudaGetSymbolAddress((void**)&bufB, g_bufB);
    uint32_t* wp128;
    uint32_t* wp64;
    cudaGetSymbolAddress((void**)&wp128, g_w128p);
    cudaGetSymbolAddress((void**)&wp64, g_w64p);
    auto W128 = [&](int m, int plane) { return wp128 + ((size_t)m * 2 + plane) * 64 * 136; };
    auto W64  = [&](int plane) { return wp64 + (size_t)plane * 64 * 72; };

    const int NB_N  = (N_NODES + 255) / 256;
    const int NB_E  = (N_EDGES + 255) / 256;
    const int NB_SC = (N_NODES + SCAN_BS - 1) / SCAN_BS;
    const int GEMM_BLOCKS = (N_NODES + 63) / 64;          // 1563
    const int AGG_BLOCKS  = (N_NODES * 32 + 255) / 256;

    const int SMEM128 = 2 * 17408 + 2 * 64 * 136 * 4;     // 104448
    const int SMEM64  = 2 * 17408 + 2 * 64 * 72 * 4;      // 71680
    cudaFuncSetAttribute(k_gemm_mma<128>, cudaFuncAttributeMaxDynamicSharedMemorySize, SMEM128);
    cudaFuncSetAttribute(k_gemm_mma<64>,  cudaFuncAttributeMaxDynamicSharedMemorySize, SMEM64);

    // #1..#3: preproc not needed by gemm1 (ncu slot alignment)
    k_init_nodes<<<NB_N, 256>>>();
    k_edge_degree<<<NB_E, 256>>>(ei, ew);
    k_wconv<<<4, 256>>>(W1, W2, W3, W4);
    // #4: gemm layer 1 (captured by ncu -s/-c window)
    k_gemm_mma<128><<<GEMM_BLOCKS, 256, SMEM128>>>(x, W128(0, 0), W128(0, 1), bufA);
    // #5..#8: rest of preprocessing (dinv fused into scanA)
    k_scanA<<<NB_SC, SCAN_BS>>>();
    k_scanB<<<1, 32>>>(NB_SC);
    k_scanC<<<NB_SC, SCAN_BS>>>();
    k_place<<<NB_E, 256>>>(ei, ew);
    // #9..: layers
    k_agg<128, true><<<AGG_BLOCKS, 256>>>(bufA, b1, bufB);

    k_gemm_mma<128><<<GEMM_BLOCKS, 256, SMEM128>>>(bufB, W128(1, 0), W128(1, 1), bufA);
    k_agg<128, true><<<AGG_BLOCKS, 256>>>(bufA, b2, bufB);

    k_gemm_mma<128><<<GEMM_BLOCKS, 256, SMEM128>>>(bufB, W128(2, 0), W128(2, 1), bufA);
    k_agg<128, true><<<AGG_BLOCKS, 256>>>(bufA, b3, bufB);

    k_gemm_mma<64><<<GEMM_BLOCKS, 256, SMEM64>>>(bufB, W64(0), W64(1), bufA);
    k_agg<64, false><<<AGG_BLOCKS, 256>>>(bufA, b4, out);
}

// round 14
// speedup vs baseline: 1.2195x; 1.2195x over previous
#include <cuda_runtime.h>
#include <cuda_bf16.h>
#include <cuda_fp16.h>
#include <cstdint>

// ---------------------------------------------------------------------------
// GCN: 4 layers, N=100000, E=1600000, 128->128->128->128->64
//   - intermediate features H stored fp16 (fp32 accumulate everywhere)
//   - split-bf16 mma.sync GEMM (R11 mainloop: pass-split, ldmatrix A)
//   - warp-per-node CSR aggregation, gathers half2, fused bias+relu
//   - gemm1 at launch slot #4 for ncu capture
// ---------------------------------------------------------------------------

#define N_NODES 100000
#define N_EDGES 1600000
#define DIM 128

// ----------------------------- scratch --------------------------------------
__device__ float g_deg[N_NODES];
__device__ float g_dinv[N_NODES];
__device__ float g_self[N_NODES];
__device__ int   g_counts[N_NODES];
__device__ int   g_offsets[N_NODES + 1];
__device__ int   g_cursor[N_NODES];
__device__ int   g_blocksums[256];
__device__ int2  g_edges[N_EDGES];
__device__ __half g_bufA[(size_t)N_NODES * DIM];
__device__ __half g_bufB[(size_t)N_NODES * DIM];
// packed W planes: [matrix][plane(hi=0,lo=1)][(k/2)*WN + n]
__device__ uint32_t g_w128p[3][2][64 * 136];
__device__ uint32_t g_w64p[2][64 * 72];

// ----------------------------- preprocessing --------------------------------
__global__ void k_init_nodes() {
    int i = blockIdx.x * blockDim.x + threadIdx.x;
    if (i < N_NODES) {
        g_deg[i]    = 1.0f;
        g_counts[i] = 0;
        g_cursor[i] = 0;
    }
}

__global__ void k_edge_degree(const int* __restrict__ ei, const float* __restrict__ w) {
    int e = blockIdx.x * blockDim.x + threadIdx.x;
    if (e < N_EDGES) {
        int dst = ei[N_EDGES + e];
        atomicAdd(&g_deg[dst], w[e]);
        atomicAdd(&g_counts[dst], 1);
    }
}

#define SCAN_BS 1024
__global__ void k_scanA() {
    __shared__ int s[SCAN_BS];
    int t = threadIdx.x;
    int i = blockIdx.x * SCAN_BS + t;
    if (i < N_NODES) {
        float d = g_deg[i];
        float r = (d > 0.0f) ? rsqrtf(d) : 0.0f;
        g_dinv[i] = r;
        g_self[i] = r * r;
    }
    int v = (i < N_NODES) ? g_counts[i] : 0;
    s[t] = v;
    __syncthreads();
    for (int off = 1; off < SCAN_BS; off <<= 1) {
        int x = (t >= off) ? s[t - off] : 0;
        __syncthreads();
        s[t] += x;
        __syncthreads();
    }
    if (i < N_NODES) g_offsets[i + 1] = s[t];
    if (t == SCAN_BS - 1) g_blocksums[blockIdx.x] = s[t];
}

__global__ void k_scanB(int nblocks) {
    if (threadIdx.x == 0 && blockIdx.x == 0) {
        int run = 0;
        for (int b = 0; b < nblocks; b++) {
            int v = g_blocksums[b];
            g_blocksums[b] = run;
            run += v;
        }
    }
}

__global__ void k_scanC() {
    int t = threadIdx.x;
    int i = blockIdx.x * SCAN_BS + t;
    if (i < N_NODES) g_offsets[i + 1] += g_blocksums[blockIdx.x];
    if (i == 0) g_offsets[0] = 0;
}

__global__ void k_place(const int* __restrict__ ei, const float* __restrict__ w) {
    int e = blockIdx.x * blockDim.x + threadIdx.x;
    if (e < N_EDGES) {
        int src = ei[e];
        int dst = ei[N_EDGES + e];
        int pos = g_offsets[dst] + atomicAdd(&g_cursor[dst], 1);
        float nm = g_dinv[src] * w[e] * g_dinv[dst];
        g_edges[pos] = make_int2(src, __float_as_int(nm));
    }
}

// ----------------------------- one-time W conversion -------------------------
__global__ void k_wconv(const float* __restrict__ W1, const float* __restrict__ W2,
                        const float* __restrict__ W3, const float* __restrict__ W4) {
    int m = blockIdx.x;
    const float* W = (m == 0) ? W1 : (m == 1) ? W2 : (m == 2) ? W3 : W4;
    int dout = (m < 3) ? 128 : 64;
    int wn   = (m < 3) ? 136 : 72;
    uint32_t* hi = (m < 3) ? g_w128p[m][0] : g_w64p[0];
    uint32_t* lo = (m < 3) ? g_w128p[m][1] : g_w64p[1];
    int total = 128 * dout;
    for (int e = threadIdx.x; e < total; e += blockDim.x) {
        int k = e / dout, n = e % dout;
        float v = W[(size_t)k * dout + n];
        __nv_bfloat16 h = __float2bfloat16_rn(v);
        __nv_bfloat16 l = __float2bfloat16_rn(v - __bfloat162float(h));
        int word = (k >> 1) * wn + n;
        int sel  = k & 1;
        reinterpret_cast<uint16_t*>(&hi[word])[sel] = *reinterpret_cast<uint16_t*>(&h);
        reinterpret_cast<uint16_t*>(&lo[word])[sel] = *reinterpret_cast<uint16_t*>(&l);
    }
}

// ----------------------------- split-bf16 mma.sync GEMM ---------------------
__device__ __forceinline__ void mma16816(float* c, const uint32_t* a,
                                         uint32_t b0, uint32_t b1) {
    asm volatile(
        "mma.sync.aligned.m16n8k16.row.col.f32.bf16.bf16.f32 "
        "{%0,%1,%2,%3}, {%4,%5,%6,%7}, {%8,%9}, {%0,%1,%2,%3};\n"
        : "+f"(c[0]), "+f"(c[1]), "+f"(c[2]), "+f"(c[3])
        : "r"(a[0]), "r"(a[1]), "r"(a[2]), "r"(a[3]), "r"(b0), "r"(b1));
}

__device__ __forceinline__ void ldmat_x4(uint32_t* r, uint32_t saddr) {
    asm volatile(
        "ldmatrix.sync.aligned.m8n8.x4.shared.b16 {%0,%1,%2,%3}, [%4];"
        : "=r"(r[0]), "=r"(r[1]), "=r"(r[2]), "=r"(r[3]) : "r"(saddr));
}

__device__ __forceinline__ uint32_t smem_u32(const void* p) {
    return (uint32_t)__cvta_generic_to_shared(p);
}

__device__ __forceinline__ void split_store(uint16_t* XHI, uint16_t* XLO, int hw,
                                            float a, float b) {
    __nv_bfloat162 h = __floats2bfloat162_rn(a, b);
    __nv_bfloat162 l = __floats2bfloat162_rn(a - __low2float(h), b - __high2float(h));
    *reinterpret_cast<uint32_t*>(&XHI[hw]) = *reinterpret_cast<uint32_t*>(&h);
    *reinterpret_cast<uint32_t*>(&XLO[hw]) = *reinterpret_cast<uint32_t*>(&l);
}

// out[64 x DOUT] per CTA = X[64,128] @ W[128,DOUT]; TIN in {float,__half}, out fp16.
template <typename TIN, int DOUT>
__global__ void __launch_bounds__(256, 2) k_gemm_mma(const TIN* __restrict__ X,
                                                     const uint32_t* __restrict__ WHIg,
                                                     const uint32_t* __restrict__ WLOg,
                                                     __half* __restrict__ out) {
    constexpr int XP = 136;
    constexpr int WN = (DOUT == 128) ? 136 : 72;
    constexpr int NT = DOUT / 32;
    constexpr int X_BYTES = 64 * XP * 2;          // 17408
    constexpr int W_WORDS = 64 * WN;

    extern __shared__ __align__(16) char smem[];
    uint16_t* XHI = reinterpret_cast<uint16_t*>(smem);
    uint16_t* XLO = reinterpret_cast<uint16_t*>(smem + X_BYTES);
    uint32_t* WHI = reinterpret_cast<uint32_t*>(smem + 2 * X_BYTES);
    uint32_t* WLO = WHI + W_WORDS;

    const int tid  = threadIdx.x;
    const int warp = tid >> 5;
    const int lane = tid & 31;
    const int g    = lane >> 2;
    const int tg   = lane & 3;
    const int row0 = blockIdx.x * 64;

    // ---- stage W planes ----------------------------------------------------
    {
        constexpr int NV4 = W_WORDS / 4;
        uint4* dh = reinterpret_cast<uint4*>(WHI);
        uint4* dl = reinterpret_cast<uint4*>(WLO);
        const uint4* sh = reinterpret_cast<const uint4*>(WHIg);
        const uint4* sl = reinterpret_cast<const uint4*>(WLOg);
        for (int i = tid; i < NV4; i += 256) { dh[i] = sh[i]; dl[i] = sl[i]; }
    }

    // ---- stage X: TIN -> bf16 hi/lo [row][k] -------------------------------
    if constexpr (sizeof(TIN) == 4) {
#pragma unroll
        for (int i = 0; i < 8; i++) {
            int s   = tid + i * 256;
            int r   = s >> 5;
            int k4  = (s & 31) * 4;
            int grow = row0 + r;
            float4 v = make_float4(0.f, 0.f, 0.f, 0.f);
            if (grow < N_NODES)
                v = *reinterpret_cast<const float4*>(
                    &reinterpret_cast<const float*>(X)[(size_t)grow * DIM + k4]);
            int hw = r * XP + k4;
            split_store(XHI, XLO, hw,     v.x, v.y);
            split_store(XHI, XLO, hw + 2, v.z, v.w);
        }
    } else {
#pragma unroll
        for (int i = 0; i < 4; i++) {
            int s   = tid + i * 256;              // 0..1023 uint4s (8 halves each)
            int r   = s >> 4;                     // row 0..63
            int k8  = (s & 15) * 8;
            int grow = row0 + r;
            uint4 raw = make_uint4(0, 0, 0, 0);
            if (grow < N_NODES)
                raw = *reinterpret_cast<const uint4*>(
                    &reinterpret_cast<const __half*>(X)[(size_t)grow * DIM + k8]);
            int hw = r * XP + k8;
            uint32_t words[4] = {raw.x, raw.y, raw.z, raw.w};
#pragma unroll
            for (int j = 0; j < 4; j++) {
                float2 f = __half22float2(*reinterpret_cast<__half2*>(&words[j]));
                split_store(XHI, XLO, hw + j * 2, f.x, f.y);
            }
        }
    }
    __syncthreads();

    // ---- warp geometry -----------------------------------------------------
    const int rg = warp & 1;
    const int cg = warp >> 1;
    const int nbase = cg * (NT * 8);

    const int li  = lane & 7;
    const int grp = lane >> 3;
    const uint32_t aoff0 =
        ((uint32_t)(rg * 32 + li + (grp & 1) * 8) * XP + (grp >> 1) * 8) * 2;
    const uint32_t aoff1 = aoff0 + 16 * XP * 2;

    const uint32_t xhi_s = smem_u32(XHI);
    const uint32_t xlo_s = smem_u32(XLO);

    float acc[2][NT][4];
#pragma unroll
    for (int mb = 0; mb < 2; mb++)
#pragma unroll
        for (int nt = 0; nt < NT; nt++)
#pragma unroll
            for (int c = 0; c < 4; c++) acc[mb][nt][c] = 0.0f;

#pragma unroll 1
    for (int pass = 0; pass < 3; pass++) {
        const uint32_t xs = (pass < 2) ? xhi_s : xlo_s;
        const uint32_t* B = (pass == 1) ? WLO : WHI;
#pragma unroll
        for (int ks = 0; ks < 8; ks++) {
            uint32_t a0[4], a1[4];
            ldmat_x4(a0, xs + aoff0 + ks * 32);
            ldmat_x4(a1, xs + aoff1 + ks * 32);
            const int kp = ks * 8 + tg;
#pragma unroll
            for (int nt = 0; nt < NT; nt++) {
                int n = nbase + nt * 8 + g;
                uint32_t b0 = B[kp * WN + n];
                uint32_t b1 = B[(kp + 4) * WN + n];
                mma16816(acc[0][nt], a0, b0, b1);
                mma16816(acc[1][nt], a1, b0, b1);
            }
        }
    }

    // ---- epilogue: half2 fragment stores -----------------------------------
#pragma unroll
    for (int mb = 0; mb < 2; mb++) {
        int r0g = row0 + rg * 32 + mb * 16 + g;
#pragma unroll
        for (int nt = 0; nt < NT; nt++) {
            int col = nbase + nt * 8 + tg * 2;
            if (r0g < N_NODES)
                *reinterpret_cast<__half2*>(&out[(size_t)r0g * DOUT + col]) =
                    __floats2half2_rn(acc[mb][nt][0], acc[mb][nt][1]);
            if (r0g + 8 < N_NODES)
                *reinterpret_cast<__half2*>(&out[(size_t)(r0g + 8) * DOUT + col]) =
                    __floats2half2_rn(acc[mb][nt][2], acc[mb][nt][3]);
        }
    }
}

// ----------------------------- aggregation: warp per node -------------------
// H fp16; accumulate fp32; TOUT = __half (hidden layers) or float (final).
template <int DOUT, bool RELU, typename TOUT>
__global__ void __launch_bounds__(256) k_agg(const __half* __restrict__ H,
                                             const float* __restrict__ bias,
                                             TOUT* __restrict__ out) {
    int node = (blockIdx.x * blockDim.x + threadIdx.x) >> 5;
    int lane = threadIdx.x & 31;
    if (node >= N_NODES) return;

    constexpr int V = DOUT / 64;   // half2 pairs per lane: 2 (128) or 1 (64)

    float2 acc[V];
    float s = g_self[node];
    {
        const __half2* hp = reinterpret_cast<const __half2*>(
            &H[(size_t)node * DOUT + lane * (V * 2)]);
#pragma unroll
        for (int c = 0; c < V; c++) {
            float2 f = __half22float2(hp[c]);
            acc[c].x = s * f.x;
            acc[c].y = s * f.y;
        }
    }

    const int2* __restrict__ ep = g_edges;
    int beg = g_offsets[node];
    int end = g_offsets[node + 1];

    int j = beg;
    for (; j + 4 <= end; j += 4) {
        int2 e0 = ep[j], e1 = ep[j + 1], e2 = ep[j + 2], e3 = ep[j + 3];
        float n0 = __int_as_float(e0.y), n1 = __int_as_float(e1.y);
        float n2 = __int_as_float(e2.y), n3 = __int_as_float(e3.y);
        const __half2* h0 = reinterpret_cast<const __half2*>(
            &H[(size_t)e0.x * DOUT + lane * (V * 2)]);
        const __half2* h1 = reinterpret_cast<const __half2*>(
            &H[(size_t)e1.x * DOUT + lane * (V * 2)]);
        const __half2* h2 = reinterpret_cast<const __half2*>(
            &H[(size_t)e2.x * DOUT + lane * (V * 2)]);
        const __half2* h3 = reinterpret_cast<const __half2*>(
            &H[(size_t)e3.x * DOUT + lane * (V * 2)]);
        if constexpr (V == 2) {
            uint2 r0 = *reinterpret_cast<const uint2*>(h0);
            uint2 r1 = *reinterpret_cast<const uint2*>(h1);
            uint2 r2 = *reinterpret_cast<const uint2*>(h2);
            uint2 r3 = *reinterpret_cast<const uint2*>(h3);
            float2 f;
            f = __half22float2(*reinterpret_cast<__half2*>(&r0.x));
            acc[0].x += n0 * f.x; acc[0].y += n0 * f.y;
            f = __half22float2(*reinterpret_cast<__half2*>(&r0.y));
            acc[1].x += n0 * f.x; acc[1].y += n0 * f.y;
            f = __half22float2(*reinterpret_cast<__half2*>(&r1.x));
            acc[0].x += n1 * f.x; acc[0].y += n1 * f.y;
            f = __half22float2(*reinterpret_cast<__half2*>(&r1.y));
            acc[1].x += n1 * f.x; acc[1].y += n1 * f.y;
            f = __half22float2(*reinterpret_cast<__half2*>(&r2.x));
            acc[0].x += n2 * f.x; acc[0].y += n2 * f.y;
            f = __half22float2(*reinterpret_cast<__half2*>(&r2.y));
            acc[1].x += n2 * f.x; acc[1].y += n2 * f.y;
            f = __half22float2(*reinterpret_cast<__half2*>(&r3.x));
            acc[0].x += n3 * f.x; acc[0].y += n3 * f.y;
            f = __half22float2(*reinterpret_cast<__half2*>(&r3.y));
            acc[1].x += n3 * f.x; acc[1].y += n3 * f.y;
        } else {
            float2 f;
            f = __half22float2(h0[0]); acc[0].x += n0 * f.x; acc[0].y += n0 * f.y;
            f = __half22float2(h1[0]); acc[0].x += n1 * f.x; acc[0].y += n1 * f.y;
            f = __half22float2(h2[0]); acc[0].x += n2 * f.x; acc[0].y += n2 * f.y;
            f = __half22float2(h3[0]); acc[0].x += n3 * f.x; acc[0].y += n3 * f.y;
        }
    }
    for (; j < end; j++) {
        int2 e = ep[j];
        float nm = __int_as_float(e.y);
        const __half2* h = reinterpret_cast<const __half2*>(
            &H[(size_t)e.x * DOUT + lane * (V * 2)]);
#pragma unroll
        for (int c = 0; c < V; c++) {
            float2 f = __half22float2(h[c]);
            acc[c].x += nm * f.x;
            acc[c].y += nm * f.y;
        }
    }

    // bias + relu + store
#pragma unroll
    for (int c = 0; c < V; c++) {
        float2 b = *reinterpret_cast<const float2*>(&bias[lane * (V * 2) + c * 2]);
        acc[c].x += b.x;
        acc[c].y += b.y;
        if (RELU) {
            acc[c].x = fmaxf(acc[c].x, 0.0f);
            acc[c].y = fmaxf(acc[c].y, 0.0f);
        }
    }
    if constexpr (sizeof(TOUT) == 2) {
        __half2* op = reinterpret_cast<__half2*>(
            &reinterpret_cast<__half*>(out)[(size_t)node * DOUT + lane * (V * 2)]);
#pragma unroll
        for (int c = 0; c < V; c++) op[c] = __floats2half2_rn(acc[c].x, acc[c].y);
    } else {
        float* op = &reinterpret_cast<float*>(out)[(size_t)node * DOUT + lane * (V * 2)];
#pragma unroll
        for (int c = 0; c < V; c++)
            *reinterpret_cast<float2*>(&op[c * 2]) = acc[c];
    }
}

// ----------------------------- launch ---------------------------------------
extern "C" void kernel_launch(void* const* d_in, const int* in_sizes, int n_in,
                              void* d_out, int out_size) {
    const float* x  = (const float*)d_in[0];
    const float* ew = (const float*)d_in[1];
    const int*   ei = (const int*)d_in[2];
    const float* W1 = (const float*)d_in[3];
    const float* b1 = (const float*)d_in[4];
    const float* W2 = (const float*)d_in[5];
    const float* b2 = (const float*)d_in[6];
    const float* W3 = (const float*)d_in[7];
    const float* b3 = (const float*)d_in[8];
    const float* W4 = (const float*)d_in[9];
    const float* b4 = (const float*)d_in[10];
    float* out = (float*)d_out;

    __half *bufA, *bufB;
    cudaGetSymbolAddress((void**)&bufA, g_bufA);
    cudaGetSymbolAddress((void**)&bufB, g_bufB);
    uint32_t* wp128;
    uint32_t* wp64;
    cudaGetSymbolAddress((void**)&wp128, g_w128p);
    cudaGetSymbolAddress((void**)&wp64, g_w64p);
    auto W128 = [&](int m, int plane) { return wp128 + ((size_t)m * 2 + plane) * 64 * 136; };
    auto W64  = [&](int plane) { return wp64 + (size_t)plane * 64 * 72; };

    const int NB_N  = (N_NODES + 255) / 256;
    const int NB_E  = (N_EDGES + 255) / 256;
    const int NB_SC = (N_NODES + SCAN_BS - 1) / SCAN_BS;
    const int GEMM_BLOCKS = (N_NODES + 63) / 64;
    const int AGG_BLOCKS  = (N_NODES * 32 + 255) / 256;

    const int SMEM128 = 2 * 17408 + 2 * 64 * 136 * 4;     // 104448
    const int SMEM64  = 2 * 17408 + 2 * 64 * 72 * 4;      // 71680
    cudaFuncSetAttribute(k_gemm_mma<float, 128>,
                         cudaFuncAttributeMaxDynamicSharedMemorySize, SMEM128);
    cudaFuncSetAttribute(k_gemm_mma<__half, 128>,
                         cudaFuncAttributeMaxDynamicSharedMemorySize, SMEM128);
    cudaFuncSetAttribute(k_gemm_mma<__half, 64>,
                         cudaFuncAttributeMaxDynamicSharedMemorySize, SMEM64);

    // #1..#3: preproc not needed by gemm1 (ncu slot alignment)
    k_init_nodes<<<NB_N, 256>>>();
    k_edge_degree<<<NB_E, 256>>>(ei, ew);
    k_wconv<<<4, 256>>>(W1, W2, W3, W4);
    // #4: gemm layer 1 (captured by ncu -s/-c window)
    k_gemm_mma<float, 128><<<GEMM_BLOCKS, 256, SMEM128>>>(x, W128(0, 0), W128(0, 1), bufA);
    // #5..#8: rest of preprocessing
    k_scanA<<<NB_SC, SCAN_BS>>>();
    k_scanB<<<1, 32>>>(NB_SC);
    k_scanC<<<NB_SC, SCAN_BS>>>();
    k_place<<<NB_E, 256>>>(ei, ew);
    // #9..: layers
    k_agg<128, true, __half><<<AGG_BLOCKS, 256>>>(bufA, b1, bufB);

    k_gemm_mma<__half, 128><<<GEMM_BLOCKS, 256, SMEM128>>>(bufB, W128(1, 0), W128(1, 1), bufA);
    k_agg<128, true, __half><<<AGG_BLOCKS, 256>>>(bufA, b2, bufB);

    k_gemm_mma<__half, 128><<<GEMM_BLOCKS, 256, SMEM128>>>(bufB, W128(2, 0), W128(2, 1), bufA);
    k_agg<128, true, __half><<<AGG_BLOCKS, 256>>>(bufA, b3, bufB);

    k_gemm_mma<__half, 64><<<GEMM_BLOCKS, 256, SMEM64>>>(bufB, W64(0), W64(1), bufA);
    k_agg<64, false, float><<<AGG_BLOCKS, 256>>>(bufA, b4, out);
}

// round 15
// speedup vs baseline: 1.2944x; 1.0614x over previous
#include <cuda_runtime.h>
#include <cuda_fp16.h>
#include <cstdint>

// ---------------------------------------------------------------------------
// GCN: 4 layers, N=100000, E=1600000, 128->128->128->128->64
//   - intermediate features H stored fp16 (fp32 accumulate everywhere)
//   - fp16 HMMA GEMM, W split into fp16 hi+lo planes (2 fused combos),
//     X single-plane fp16, ldmatrix A
//   - warp-per-node CSR aggregation, gathers half2, fused bias+relu
//   - gemm1 at launch slot #4 for ncu capture
// ---------------------------------------------------------------------------

#define N_NODES 100000
#define N_EDGES 1600000
#define DIM 128

// ----------------------------- scratch --------------------------------------
__device__ float g_deg[N_NODES];
__device__ float g_dinv[N_NODES];
__device__ float g_self[N_NODES];
__device__ int   g_counts[N_NODES];
__device__ int   g_offsets[N_NODES + 1];
__device__ int   g_cursor[N_NODES];
__device__ int   g_blocksums[256];
__device__ int2  g_edges[N_EDGES];
__device__ __half g_bufA[(size_t)N_NODES * DIM];
__device__ __half g_bufB[(size_t)N_NODES * DIM];
// packed W planes (fp16 pairs): [matrix][plane(hi=0,lo=1)][(k/2)*WN + n]
__device__ uint32_t g_w128p[3][2][64 * 136];
__device__ uint32_t g_w64p[2][64 * 72];

// ----------------------------- preprocessing --------------------------------
__global__ void k_init_nodes() {
    int i = blockIdx.x * blockDim.x + threadIdx.x;
    if (i < N_NODES) {
        g_deg[i]    = 1.0f;
        g_counts[i] = 0;
        g_cursor[i] = 0;
    }
}

__global__ void k_edge_degree(const int* __restrict__ ei, const float* __restrict__ w) {
    int e = blockIdx.x * blockDim.x + threadIdx.x;
    if (e < N_EDGES) {
        int dst = ei[N_EDGES + e];
        atomicAdd(&g_deg[dst], w[e]);
        atomicAdd(&g_counts[dst], 1);
    }
}

#define SCAN_BS 1024
__global__ void k_scanA() {
    __shared__ int s[SCAN_BS];
    int t = threadIdx.x;
    int i = blockIdx.x * SCAN_BS + t;
    if (i < N_NODES) {
        float d = g_deg[i];
        float r = (d > 0.0f) ? rsqrtf(d) : 0.0f;
        g_dinv[i] = r;
        g_self[i] = r * r;
    }
    int v = (i < N_NODES) ? g_counts[i] : 0;
    s[t] = v;
    __syncthreads();
    for (int off = 1; off < SCAN_BS; off <<= 1) {
        int x = (t >= off) ? s[t - off] : 0;
        __syncthreads();
        s[t] += x;
        __syncthreads();
    }
    if (i < N_NODES) g_offsets[i + 1] = s[t];
    if (t == SCAN_BS - 1) g_blocksums[blockIdx.x] = s[t];
}

__global__ void k_scanB(int nblocks) {
    if (threadIdx.x == 0 && blockIdx.x == 0) {
        int run = 0;
        for (int b = 0; b < nblocks; b++) {
            int v = g_blocksums[b];
            g_blocksums[b] = run;
            run += v;
        }
    }
}

__global__ void k_scanC() {
    int t = threadIdx.x;
    int i = blockIdx.x * SCAN_BS + t;
    if (i < N_NODES) g_offsets[i + 1] += g_blocksums[blockIdx.x];
    if (i == 0) g_offsets[0] = 0;
}

__global__ void k_place(const int* __restrict__ ei, const float* __restrict__ w) {
    int e = blockIdx.x * blockDim.x + threadIdx.x;
    if (e < N_EDGES) {
        int src = ei[e];
        int dst = ei[N_EDGES + e];
        int pos = g_offsets[dst] + atomicAdd(&g_cursor[dst], 1);
        float nm = g_dinv[src] * w[e] * g_dinv[dst];
        g_edges[pos] = make_int2(src, __float_as_int(nm));
    }
}

// ----------------------------- one-time W conversion (fp16 hi/lo) -----------
__global__ void k_wconv(const float* __restrict__ W1, const float* __restrict__ W2,
                        const float* __restrict__ W3, const float* __restrict__ W4) {
    int m = blockIdx.x;
    const float* W = (m == 0) ? W1 : (m == 1) ? W2 : (m == 2) ? W3 : W4;
    int dout = (m < 3) ? 128 : 64;
    int wn   = (m < 3) ? 136 : 72;
    uint32_t* hi = (m < 3) ? g_w128p[m][0] : g_w64p[0];
    uint32_t* lo = (m < 3) ? g_w128p[m][1] : g_w64p[1];
    int total = 128 * dout;
    for (int e = threadIdx.x; e < total; e += blockDim.x) {
        int k = e / dout, n = e % dout;
        float v = W[(size_t)k * dout + n];
        __half h = __float2half_rn(v);
        __half l = __float2half_rn(v - __half2float(h));
        int word = (k >> 1) * wn + n;
        int sel  = k & 1;
        reinterpret_cast<uint16_t*>(&hi[word])[sel] = *reinterpret_cast<uint16_t*>(&h);
        reinterpret_cast<uint16_t*>(&lo[word])[sel] = *reinterpret_cast<uint16_t*>(&l);
    }
}

// ----------------------------- fp16 mma.sync GEMM ---------------------------
__device__ __forceinline__ void mma16816(float* c, const uint32_t* a,
                                         uint32_t b0, uint32_t b1) {
    asm volatile(
        "mma.sync.aligned.m16n8k16.row.col.f32.f16.f16.f32 "
        "{%0,%1,%2,%3}, {%4,%5,%6,%7}, {%8,%9}, {%0,%1,%2,%3};\n"
        : "+f"(c[0]), "+f"(c[1]), "+f"(c[2]), "+f"(c[3])
        : "r"(a[0]), "r"(a[1]), "r"(a[2]), "r"(a[3]), "r"(b0), "r"(b1));
}

__device__ __forceinline__ void ldmat_x4(uint32_t* r, uint32_t saddr) {
    asm volatile(
        "ldmatrix.sync.aligned.m8n8.x4.shared.b16 {%0,%1,%2,%3}, [%4];"
        : "=r"(r[0]), "=r"(r[1]), "=r"(r[2]), "=r"(r[3]) : "r"(saddr));
}

__device__ __forceinline__ uint32_t smem_u32(const void* p) {
    return (uint32_t)__cvta_generic_to_shared(p);
}

// out[64 x DOUT] per CTA = X[64,128] @ W[128,DOUT]; TIN in {float,__half}, out fp16.
// X smem: fp16 [64][XP=136 halfwords], single plane (exact).
// W smem: packed fp16-pair words uint32[(k/2)][WN], hi + lo planes.
template <typename TIN, int DOUT>
__global__ void __launch_bounds__(256, 2) k_gemm_mma(const TIN* __restrict__ X,
                                                     const uint32_t* __restrict__ WHIg,
                                                     const uint32_t* __restrict__ WLOg,
                                                     __half* __restrict__ out) {
    constexpr int XP = 136;
    constexpr int WN = (DOUT == 128) ? 136 : 72;
    constexpr int NT = DOUT / 32;                 // n-tiles per warp (4 / 2)
    constexpr int X_BYTES = 64 * XP * 2;          // 17408
    constexpr int W_WORDS = 64 * WN;

    extern __shared__ __align__(16) char smem[];
    uint16_t* XS  = reinterpret_cast<uint16_t*>(smem);
    uint32_t* WHI = reinterpret_cast<uint32_t*>(smem + X_BYTES);
    uint32_t* WLO = WHI + W_WORDS;

    const int tid  = threadIdx.x;
    const int warp = tid >> 5;
    const int lane = tid & 31;
    const int g    = lane >> 2;
    const int tg   = lane & 3;
    const int row0 = blockIdx.x * 64;

    // ---- stage W planes (uint4 copy from packed gmem) ----------------------
    {
        constexpr int NV4 = W_WORDS / 4;
        uint4* dh = reinterpret_cast<uint4*>(WHI);
        uint4* dl = reinterpret_cast<uint4*>(WLO);
        const uint4* sh = reinterpret_cast<const uint4*>(WHIg);
        const uint4* sl = reinterpret_cast<const uint4*>(WLOg);
        for (int i = tid; i < NV4; i += 256) { dh[i] = sh[i]; dl[i] = sl[i]; }
    }

    // ---- stage X: TIN -> fp16 [row][k], single plane -----------------------
    if constexpr (sizeof(TIN) == 4) {
#pragma unroll
        for (int i = 0; i < 8; i++) {
            int s   = tid + i * 256;              // 0..2047 float4s
            int r   = s >> 5;                     // row 0..63
            int k4  = (s & 31) * 4;
            int grow = row0 + r;
            float4 v = make_float4(0.f, 0.f, 0.f, 0.f);
            if (grow < N_NODES)
                v = *reinterpret_cast<const float4*>(
                    &reinterpret_cast<const float*>(X)[(size_t)grow * DIM + k4]);
            int hw = r * XP + k4;
            __half2 p0 = __floats2half2_rn(v.x, v.y);
            __half2 p1 = __floats2half2_rn(v.z, v.w);
            *reinterpret_cast<uint32_t*>(&XS[hw])     = *reinterpret_cast<uint32_t*>(&p0);
            *reinterpret_cast<uint32_t*>(&XS[hw + 2]) = *reinterpret_cast<uint32_t*>(&p1);
        }
    } else {
#pragma unroll
        for (int i = 0; i < 4; i++) {
            int s   = tid + i * 256;              // 0..1023 uint4s (8 halves each)
            int r   = s >> 4;                     // row 0..63
            int k8  = (s & 15) * 8;
            int grow = row0 + r;
            uint4 raw = make_uint4(0, 0, 0, 0);
            if (grow < N_NODES)
                raw = *reinterpret_cast<const uint4*>(
                    &reinterpret_cast<const __half*>(X)[(size_t)grow * DIM + k8]);
            int hw = r * XP + k8;
            *reinterpret_cast<uint32_t*>(&XS[hw])     = raw.x;
            *reinterpret_cast<uint32_t*>(&XS[hw + 2]) = raw.y;
            *reinterpret_cast<uint32_t*>(&XS[hw + 4]) = raw.z;
            *reinterpret_cast<uint32_t*>(&XS[hw + 6]) = raw.w;
        }
    }
    __syncthreads();

    // ---- warp geometry -----------------------------------------------------
    const int rg = warp & 1;                      // row group: rows rg*32..+31
    const int cg = warp >> 1;                     // col group: cols cg*(DOUT/4)
    const int nbase = cg * (NT * 8);

    const int li  = lane & 7;
    const int grp = lane >> 3;
    const uint32_t aoff0 =
        ((uint32_t)(rg * 32 + li + (grp & 1) * 8) * XP + (grp >> 1) * 8) * 2;
    const uint32_t aoff1 = aoff0 + 16 * XP * 2;

    const uint32_t xs_s = smem_u32(XS);

    float acc[2][NT][4];
#pragma unroll
    for (int mb = 0; mb < 2; mb++)
#pragma unroll
        for (int nt = 0; nt < NT; nt++)
#pragma unroll
            for (int c = 0; c < 4; c++) acc[mb][nt][c] = 0.0f;

    // ---- fused mainloop: per k-step load A once, both W planes, 16 HMMA ----
#pragma unroll
    for (int ks = 0; ks < 8; ks++) {
        uint32_t a0[4], a1[4];
        ldmat_x4(a0, xs_s + aoff0 + ks * 32);     // ks*16 halfwords *2 bytes
        ldmat_x4(a1, xs_s + aoff1 + ks * 32);
        const int kp = ks * 8 + tg;
#pragma unroll
        for (int nt = 0; nt < NT; nt++) {
            int n = nbase + nt * 8 + g;
            uint32_t bh0 = WHI[kp * WN + n];
            uint32_t bh1 = WHI[(kp + 4) * WN + n];
            uint32_t bl0 = WLO[kp * WN + n];
            uint32_t bl1 = WLO[(kp + 4) * WN + n];
            mma16816(acc[0][nt], a0, bh0, bh1);   // X * Whi
            mma16816(acc[1][nt], a1, bh0, bh1);
            mma16816(acc[0][nt], a0, bl0, bl1);   // X * Wlo
            mma16816(acc[1][nt], a1, bl0, bl1);
        }
    }

    // ---- epilogue: half2 fragment stores -----------------------------------
#pragma unroll
    for (int mb = 0; mb < 2; mb++) {
        int r0g = row0 + rg * 32 + mb * 16 + g;
#pragma unroll
        for (int nt = 0; nt < NT; nt++) {
            int col = nbase + nt * 8 + tg * 2;
            if (r0g < N_NODES)
                *reinterpret_cast<__half2*>(&out[(size_t)r0g * DOUT + col]) =
                    __floats2half2_rn(acc[mb][nt][0], acc[mb][nt][1]);
            if (r0g + 8 < N_NODES)
                *reinterpret_cast<__half2*>(&out[(size_t)(r0g + 8) * DOUT + col]) =
                    __floats2half2_rn(acc[mb][nt][2], acc[mb][nt][3]);
        }
    }
}

// ----------------------------- aggregation: warp per node -------------------
// H fp16; accumulate fp32; TOUT = __half (hidden layers) or float (final).
template <int DOUT, bool RELU, typename TOUT>
__global__ void __launch_bounds__(256) k_agg(const __half* __restrict__ H,
                                             const float* __restrict__ bias,
                                             TOUT* __restrict__ out) {
    int node = (blockIdx.x * blockDim.x + threadIdx.x) >> 5;
    int lane = threadIdx.x & 31;
    if (node >= N_NODES) return;

    constexpr int V = DOUT / 64;   // half2 pairs per lane: 2 (128) or 1 (64)

    float2 acc[V];
    float s = g_self[node];
    {
        const __half2* hp = reinterpret_cast<const __half2*>(
            &H[(size_t)node * DOUT + lane * (V * 2)]);
#pragma unroll
        for (int c = 0; c < V; c++) {
            float2 f = __half22float2(hp[c]);
            acc[c].x = s * f.x;
            acc[c].y = s * f.y;
        }
    }

    const int2* __restrict__ ep = g_edges;
    int beg = g_offsets[node];
    int end = g_offsets[node + 1];

    int j = beg;
    for (; j + 4 <= end; j += 4) {
        int2 e0 = ep[j], e1 = ep[j + 1], e2 = ep[j + 2], e3 = ep[j + 3];
        float n0 = __int_as_float(e0.y), n1 = __int_as_float(e1.y);
        float n2 = __int_as_float(e2.y), n3 = __int_as_float(e3.y);
        const __half2* h0 = reinterpret_cast<const __half2*>(
            &H[(size_t)e0.x * DOUT + lane * (V * 2)]);
        const __half2* h1 = reinterpret_cast<const __half2*>(
            &H[(size_t)e1.x * DOUT + lane * (V * 2)]);
        const __half2* h2 = reinterpret_cast<const __half2*>(
            &H[(size_t)e2.x * DOUT + lane * (V * 2)]);
        const __half2* h3 = reinterpret_cast<const __half2*>(
            &H[(size_t)e3.x * DOUT + lane * (V * 2)]);
        if constexpr (V == 2) {
            uint2 r0 = *reinterpret_cast<const uint2*>(h0);
            uint2 r1 = *reinterpret_cast<const uint2*>(h1);
            uint2 r2 = *reinterpret_cast<const uint2*>(h2);
            uint2 r3 = *reinterpret_cast<const uint2*>(h3);
            float2 f;
            f = __half22float2(*reinterpret_cast<__half2*>(&r0.x));
            acc[0].x += n0 * f.x; acc[0].y += n0 * f.y;
            f = __half22float2(*reinterpret_cast<__half2*>(&r0.y));
            acc[1].x += n0 * f.x; acc[1].y += n0 * f.y;
            f = __half22float2(*reinterpret_cast<__half2*>(&r1.x));
            acc[0].x += n1 * f.x; acc[0].y += n1 * f.y;
            f = __half22float2(*reinterpret_cast<__half2*>(&r1.y));
            acc[1].x += n1 * f.x; acc[1].y += n1 * f.y;
            f = __half22float2(*reinterpret_cast<__half2*>(&r2.x));
            acc[0].x += n2 * f.x; acc[0].y += n2 * f.y;
            f = __half22float2(*reinterpret_cast<__half2*>(&r2.y));
            acc[1].x += n2 * f.x; acc[1].y += n2 * f.y;
            f = __half22float2(*reinterpret_cast<__half2*>(&r3.x));
            acc[0].x += n3 * f.x; acc[0].y += n3 * f.y;
            f = __half22float2(*reinterpret_cast<__half2*>(&r3.y));
            acc[1].x += n3 * f.x; acc[1].y += n3 * f.y;
        } else {
            float2 f;
            f = __half22float2(h0[0]); acc[0].x += n0 * f.x; acc[0].y += n0 * f.y;
            f = __half22float2(h1[0]); acc[0].x += n1 * f.x; acc[0].y += n1 * f.y;
            f = __half22float2(h2[0]); acc[0].x += n2 * f.x; acc[0].y += n2 * f.y;
            f = __half22float2(h3[0]); acc[0].x += n3 * f.x; acc[0].y += n3 * f.y;
        }
    }
    for (; j < end; j++) {
        int2 e = ep[j];
        float nm = __int_as_float(e.y);
        const __half2* h = reinterpret_cast<const __half2*>(
            &H[(size_t)e.x * DOUT + lane * (V * 2)]);
#pragma unroll
        for (int c = 0; c < V; c++) {
            float2 f = __half22float2(h[c]);
            acc[c].x += nm * f.x;
            acc[c].y += nm * f.y;
        }
    }

    // bias + relu + store
#pragma unroll
    for (int c = 0; c < V; c++) {
        float2 b = *reinterpret_cast<const float2*>(&bias[lane * (V * 2) + c * 2]);
        acc[c].x += b.x;
        acc[c].y += b.y;
        if (RELU) {
            acc[c].x = fmaxf(acc[c].x, 0.0f);
            acc[c].y = fmaxf(acc[c].y, 0.0f);
        }
    }
    if constexpr (sizeof(TOUT) == 2) {
        __half2* op = reinterpret_cast<__half2*>(
            &reinterpret_cast<__half*>(out)[(size_t)node * DOUT + lane * (V * 2)]);
#pragma unroll
        for (int c = 0; c < V; c++) op[c] = __floats2half2_rn(acc[c].x, acc[c].y);
    } else {
        float* op = &reinterpret_cast<float*>(out)[(size_t)node * DOUT + lane * (V * 2)];
#pragma unroll
        for (int c = 0; c < V; c++)
            *reinterpret_cast<float2*>(&op[c * 2]) = acc[c];
    }
}

// ----------------------------- launch ---------------------------------------
extern "C" void kernel_launch(void* const* d_in, const int* in_sizes, int n_in,
                              void* d_out, int out_size) {
    const float* x  = (const float*)d_in[0];
    const float* ew = (const float*)d_in[1];
    const int*   ei = (const int*)d_in[2];
    const float* W1 = (const float*)d_in[3];
    const float* b1 = (const float*)d_in[4];
    const float* W2 = (const float*)d_in[5];
    const float* b2 = (const float*)d_in[6];
    const float* W3 = (const float*)d_in[7];
    const float* b3 = (const float*)d_in[8];
    const float* W4 = (const float*)d_in[9];
    const float* b4 = (const float*)d_in[10];
    float* out = (float*)d_out;

    __half *bufA, *bufB;
    cudaGetSymbolAddress((void**)&bufA, g_bufA);
    cudaGetSymbolAddress((void**)&bufB, g_bufB);
    uint32_t* wp128;
    uint32_t* wp64;
    cudaGetSymbolAddress((void**)&wp128, g_w128p);
    cudaGetSymbolAddress((void**)&wp64, g_w64p);
    auto W128 = [&](int m, int plane) { return wp128 + ((size_t)m * 2 + plane) * 64 * 136; };
    auto W64  = [&](int plane) { return wp64 + (size_t)plane * 64 * 72; };

    const int NB_N  = (N_NODES + 255) / 256;
    const int NB_E  = (N_EDGES + 255) / 256;
    const int NB_SC = (N_NODES + SCAN_BS - 1) / SCAN_BS;
    const int GEMM_BLOCKS = (N_NODES + 63) / 64;
    const int AGG_BLOCKS  = (N_NODES * 32 + 255) / 256;

    const int SMEM128 = 17408 + 2 * 64 * 136 * 4;         // 87040
    const int SMEM64  = 17408 + 2 * 64 * 72 * 4;          // 54272
    cudaFuncSetAttribute(k_gemm_mma<float, 128>,
                         cudaFuncAttributeMaxDynamicSharedMemorySize, SMEM128);
    cudaFuncSetAttribute(k_gemm_mma<__half, 128>,
                         cudaFuncAttributeMaxDynamicSharedMemorySize, SMEM128);
    cudaFuncSetAttribute(k_gemm_mma<__half, 64>,
                         cudaFuncAttributeMaxDynamicSharedMemorySize, SMEM64);

    // #1..#3: preproc not needed by gemm1 (ncu slot alignment)
    k_init_nodes<<<NB_N, 256>>>();
    k_edge_degree<<<NB_E, 256>>>(ei, ew);
    k_wconv<<<4, 256>>>(W1, W2, W3, W4);
    // #4: gemm layer 1 (captured by ncu -s/-c window)
    k_gemm_mma<float, 128><<<GEMM_BLOCKS, 256, SMEM128>>>(x, W128(0, 0), W128(0, 1), bufA);
    // #5..#8: rest of preprocessing
    k_scanA<<<NB_SC, SCAN_BS>>>();
    k_scanB<<<1, 32>>>(NB_SC);
    k_scanC<<<NB_SC, SCAN_BS>>>();
    k_place<<<NB_E, 256>>>(ei, ew);
    // #9..: layers
    k_agg<128, true, __half><<<AGG_BLOCKS, 256>>>(bufA, b1, bufB);

    k_gemm_mma<__half, 128><<<GEMM_BLOCKS, 256, SMEM128>>>(bufB, W128(1, 0), W128(1, 1), bufA);
    k_agg<128, true, __half><<<AGG_BLOCKS, 256>>>(bufA, b2, bufB);

    k_gemm_mma<__half, 128><<<GEMM_BLOCKS, 256, SMEM128>>>(bufB, W128(2, 0), W128(2, 1), bufA);
    k_agg<128, true, __half><<<AGG_BLOCKS, 256>>>(bufA, b3, bufB);

    k_gemm_mma<__half, 64><<<GEMM_BLOCKS, 256, SMEM64>>>(bufB, W64(0), W64(1), bufA);
    k_agg<64, false, float><<<AGG_BLOCKS, 256>>>(bufA, b4, out);
}

// round 16
// speedup vs baseline: 1.3778x; 1.0644x over previous
#include <cuda_runtime.h>
#include <cuda_fp16.h>
#include <cstdint>

// ---------------------------------------------------------------------------
// GCN: 4 layers, N=100000, E=1600000, 128->128->128->128->64
//   - intermediate features H stored fp16 (fp32 accumulate everywhere)
//   - fp16 HMMA GEMM, W split fp16 hi+lo (2 fused combos), X single-plane
//   - 64x64 tiles (grid.y = DOUT/64), smem 54KB -> 3 CTAs/SM
//   - warp-per-node CSR aggregation, gathers half2, fused bias+relu
//   - gemm1 at launch slot #4 for ncu capture
// ---------------------------------------------------------------------------

#define N_NODES 100000
#define N_EDGES 1600000
#define DIM 128

// ----------------------------- scratch --------------------------------------
__device__ float g_deg[N_NODES];
__device__ float g_dinv[N_NODES];
__device__ float g_self[N_NODES];
__device__ int   g_counts[N_NODES];
__device__ int   g_offsets[N_NODES + 1];
__device__ int   g_cursor[N_NODES];
__device__ int   g_blocksums[256];
__device__ int2  g_edges[N_EDGES];
__device__ __half g_bufA[(size_t)N_NODES * DIM];
__device__ __half g_bufB[(size_t)N_NODES * DIM];
// packed W planes (fp16 pairs): [matrix][plane(hi=0,lo=1)][(k/2)*WN + n]
__device__ uint32_t g_w128p[3][2][64 * 136];
__device__ uint32_t g_w64p[2][64 * 72];

// ----------------------------- preprocessing --------------------------------
__global__ void k_init_nodes() {
    int i = blockIdx.x * blockDim.x + threadIdx.x;
    if (i < N_NODES) {
        g_deg[i]    = 1.0f;
        g_counts[i] = 0;
        g_cursor[i] = 0;
    }
}

__global__ void k_edge_degree(const int* __restrict__ ei, const float* __restrict__ w) {
    int e = blockIdx.x * blockDim.x + threadIdx.x;
    if (e < N_EDGES) {
        int dst = ei[N_EDGES + e];
        atomicAdd(&g_deg[dst], w[e]);
        atomicAdd(&g_counts[dst], 1);
    }
}

#define SCAN_BS 1024
__global__ void k_scanA() {
    __shared__ int s[SCAN_BS];
    int t = threadIdx.x;
    int i = blockIdx.x * SCAN_BS + t;
    if (i < N_NODES) {
        float d = g_deg[i];
        float r = (d > 0.0f) ? rsqrtf(d) : 0.0f;
        g_dinv[i] = r;
        g_self[i] = r * r;
    }
    int v = (i < N_NODES) ? g_counts[i] : 0;
    s[t] = v;
    __syncthreads();
    for (int off = 1; off < SCAN_BS; off <<= 1) {
        int x = (t >= off) ? s[t - off] : 0;
        __syncthreads();
        s[t] += x;
        __syncthreads();
    }
    if (i < N_NODES) g_offsets[i + 1] = s[t];
    if (t == SCAN_BS - 1) g_blocksums[blockIdx.x] = s[t];
}

__global__ void k_scanB(int nblocks) {
    if (threadIdx.x == 0 && blockIdx.x == 0) {
        int run = 0;
        for (int b = 0; b < nblocks; b++) {
            int v = g_blocksums[b];
            g_blocksums[b] = run;
            run += v;
        }
    }
}

__global__ void k_scanC() {
    int t = threadIdx.x;
    int i = blockIdx.x * SCAN_BS + t;
    if (i < N_NODES) g_offsets[i + 1] += g_blocksums[blockIdx.x];
    if (i == 0) g_offsets[0] = 0;
}

__global__ void k_place(const int* __restrict__ ei, const float* __restrict__ w) {
    int e = blockIdx.x * blockDim.x + threadIdx.x;
    if (e < N_EDGES) {
        int src = ei[e];
        int dst = ei[N_EDGES + e];
        int pos = g_offsets[dst] + atomicAdd(&g_cursor[dst], 1);
        float nm = g_dinv[src] * w[e] * g_dinv[dst];
        g_edges[pos] = make_int2(src, __float_as_int(nm));
    }
}

// ----------------------------- one-time W conversion (fp16 hi/lo) -----------
__global__ void k_wconv(const float* __restrict__ W1, const float* __restrict__ W2,
                        const float* __restrict__ W3, const float* __restrict__ W4) {
    int m = blockIdx.x;
    const float* W = (m == 0) ? W1 : (m == 1) ? W2 : (m == 2) ? W3 : W4;
    int dout = (m < 3) ? 128 : 64;
    int wn   = (m < 3) ? 136 : 72;
    uint32_t* hi = (m < 3) ? g_w128p[m][0] : g_w64p[0];
    uint32_t* lo = (m < 3) ? g_w128p[m][1] : g_w64p[1];
    int total = 128 * dout;
    for (int e = threadIdx.x; e < total; e += blockDim.x) {
        int k = e / dout, n = e % dout;
        float v = W[(size_t)k * dout + n];
        __half h = __float2half_rn(v);
        __half l = __float2half_rn(v - __half2float(h));
        int word = (k >> 1) * wn + n;
        int sel  = k & 1;
        reinterpret_cast<uint16_t*>(&hi[word])[sel] = *reinterpret_cast<uint16_t*>(&h);
        reinterpret_cast<uint16_t*>(&lo[word])[sel] = *reinterpret_cast<uint16_t*>(&l);
    }
}

// ----------------------------- fp16 mma.sync GEMM ---------------------------
__device__ __forceinline__ void mma16816(float* c, const uint32_t* a,
                                         uint32_t b0, uint32_t b1) {
    asm volatile(
        "mma.sync.aligned.m16n8k16.row.col.f32.f16.f16.f32 "
        "{%0,%1,%2,%3}, {%4,%5,%6,%7}, {%8,%9}, {%0,%1,%2,%3};\n"
        : "+f"(c[0]), "+f"(c[1]), "+f"(c[2]), "+f"(c[3])
        : "r"(a[0]), "r"(a[1]), "r"(a[2]), "r"(a[3]), "r"(b0), "r"(b1));
}

__device__ __forceinline__ void ldmat_x4(uint32_t* r, uint32_t saddr) {
    asm volatile(
        "ldmatrix.sync.aligned.m8n8.x4.shared.b16 {%0,%1,%2,%3}, [%4];"
        : "=r"(r[0]), "=r"(r[1]), "=r"(r[2]), "=r"(r[3]) : "r"(saddr));
}

__device__ __forceinline__ uint32_t smem_u32(const void* p) {
    return (uint32_t)__cvta_generic_to_shared(p);
}

// Tile: 64 rows x 64 cols per CTA. grid = (rowblocks, DOUT/64).
// X smem: fp16 [64][XP=136 halfwords], single plane.
// W smem: this CTA's 64 columns, packed fp16-pair words, stride WS=72,
//         hi + lo planes (stride 72 mod 32 = 8 -> B loads conflict-free).
template <typename TIN, int DOUT>
__global__ void __launch_bounds__(256, 3) k_gemm_mma(const TIN* __restrict__ X,
                                                     const uint32_t* __restrict__ WHIg,
                                                     const uint32_t* __restrict__ WLOg,
                                                     __half* __restrict__ out) {
    constexpr int XP = 136;
    constexpr int WS = 72;                        // smem W stride (words)
    constexpr int WN_G = (DOUT == 128) ? 136 : 72;  // gmem W stride (words)
    constexpr int X_BYTES = 64 * XP * 2;          // 17408
    constexpr int W_WORDS_S = 64 * WS;            // 4608 per plane

    extern __shared__ __align__(16) char smem[];
    uint16_t* XS  = reinterpret_cast<uint16_t*>(smem);
    uint32_t* WHI = reinterpret_cast<uint32_t*>(smem + X_BYTES);
    uint32_t* WLO = WHI + W_WORDS_S;

    const int tid  = threadIdx.x;
    const int warp = tid >> 5;
    const int lane = tid & 31;
    const int g    = lane >> 2;
    const int tg   = lane & 3;
    const int row0 = blockIdx.x * 64;
    const int noff = blockIdx.y * 64;             // column offset of this CTA

    // ---- stage W planes: 64 cols from gmem, re-strided to WS=72 ------------
    {
        // 64 k-pair rows x 16 uint4 (64 words) per plane = 1024 uint4
#pragma unroll
        for (int i = 0; i < 4; i++) {
            int s   = tid + i * 256;              // 0..1023
            int row = s >> 4;
            int c4  = (s & 15) * 4;
            uint4 vh = *reinterpret_cast<const uint4*>(&WHIg[row * WN_G + noff + c4]);
            uint4 vl = *reinterpret_cast<const uint4*>(&WLOg[row * WN_G + noff + c4]);
            *reinterpret_cast<uint4*>(&WHI[row * WS + c4]) = vh;
            *reinterpret_cast<uint4*>(&WLO[row * WS + c4]) = vl;
        }
    }

    // ---- stage X: TIN -> fp16 [row][k], single plane -----------------------
    if constexpr (sizeof(TIN) == 4) {
#pragma unroll
        for (int i = 0; i < 8; i++) {
            int s   = tid + i * 256;              // 0..2047 float4s
            int r   = s >> 5;                     // row 0..63
            int k4  = (s & 31) * 4;
            int grow = row0 + r;
            float4 v = make_float4(0.f, 0.f, 0.f, 0.f);
            if (grow < N_NODES)
                v = *reinterpret_cast<const float4*>(
                    &reinterpret_cast<const float*>(X)[(size_t)grow * DIM + k4]);
            int hw = r * XP + k4;
            __half2 p0 = __floats2half2_rn(v.x, v.y);
            __half2 p1 = __floats2half2_rn(v.z, v.w);
            *reinterpret_cast<uint32_t*>(&XS[hw])     = *reinterpret_cast<uint32_t*>(&p0);
            *reinterpret_cast<uint32_t*>(&XS[hw + 2]) = *reinterpret_cast<uint32_t*>(&p1);
        }
    } else {
#pragma unroll
        for (int i = 0; i < 4; i++) {
            int s   = tid + i * 256;              // 0..1023 uint4s (8 halves each)
            int r   = s >> 4;                     // row 0..63
            int k8  = (s & 15) * 8;
            int grow = row0 + r;
            uint4 raw = make_uint4(0, 0, 0, 0);
            if (grow < N_NODES)
                raw = *reinterpret_cast<const uint4*>(
                    &reinterpret_cast<const __half*>(X)[(size_t)grow * DIM + k8]);
            int hw = r * XP + k8;
            *reinterpret_cast<uint32_t*>(&XS[hw])     = raw.x;
            *reinterpret_cast<uint32_t*>(&XS[hw + 2]) = raw.y;
            *reinterpret_cast<uint32_t*>(&XS[hw + 4]) = raw.z;
            *reinterpret_cast<uint32_t*>(&XS[hw + 6]) = raw.w;
        }
    }
    __syncthreads();

    // ---- warp geometry: 8 warps = 2 row groups x 4 col groups --------------
    const int rg = warp & 1;                      // rows rg*32..+31
    const int cg = warp >> 1;                     // cols cg*16..+15 (local)

    const int li  = lane & 7;
    const int grp = lane >> 3;
    const uint32_t aoff0 =
        ((uint32_t)(rg * 32 + li + (grp & 1) * 8) * XP + (grp >> 1) * 8) * 2;
    const uint32_t aoff1 = aoff0 + 16 * XP * 2;

    const uint32_t xs_s = smem_u32(XS);

    float acc[2][2][4];                           // [mb][nt][c]
#pragma unroll
    for (int mb = 0; mb < 2; mb++)
#pragma unroll
        for (int nt = 0; nt < 2; nt++)
#pragma unroll
            for (int c = 0; c < 4; c++) acc[mb][nt][c] = 0.0f;

    // ---- fused mainloop: per k-step load A once, both W planes, 8 HMMA -----
#pragma unroll
    for (int ks = 0; ks < 8; ks++) {
        uint32_t a0[4], a1[4];
        ldmat_x4(a0, xs_s + aoff0 + ks * 32);
        ldmat_x4(a1, xs_s + aoff1 + ks * 32);
        const int kp = ks * 8 + tg;
#pragma unroll
        for (int nt = 0; nt < 2; nt++) {
            int nl = cg * 16 + nt * 8 + g;
            uint32_t bh0 = WHI[kp * WS + nl];
            uint32_t bh1 = WHI[(kp + 4) * WS + nl];
            uint32_t bl0 = WLO[kp * WS + nl];
            uint32_t bl1 = WLO[(kp + 4) * WS + nl];
            mma16816(acc[0][nt], a0, bh0, bh1);   // X * Whi
            mma16816(acc[1][nt], a1, bh0, bh1);
            mma16816(acc[0][nt], a0, bl0, bl1);   // X * Wlo
            mma16816(acc[1][nt], a1, bl0, bl1);
        }
    }

    // ---- epilogue: half2 fragment stores -----------------------------------
#pragma unroll
    for (int mb = 0; mb < 2; mb++) {
        int r0g = row0 + rg * 32 + mb * 16 + g;
#pragma unroll
        for (int nt = 0; nt < 2; nt++) {
            int col = noff + cg * 16 + nt * 8 + tg * 2;
            if (r0g < N_NODES)
                *reinterpret_cast<__half2*>(&out[(size_t)r0g * DOUT + col]) =
                    __floats2half2_rn(acc[mb][nt][0], acc[mb][nt][1]);
            if (r0g + 8 < N_NODES)
                *reinterpret_cast<__half2*>(&out[(size_t)(r0g + 8) * DOUT + col]) =
                    __floats2half2_rn(acc[mb][nt][2], acc[mb][nt][3]);
        }
    }
}

// ----------------------------- aggregation: warp per node -------------------
// H fp16; accumulate fp32; TOUT = __half (hidden layers) or float (final).
template <int DOUT, bool RELU, typename TOUT>
__global__ void __launch_bounds__(256) k_agg(const __half* __restrict__ H,
                                             const float* __restrict__ bias,
                                             TOUT* __restrict__ out) {
    int node = (blockIdx.x * blockDim.x + threadIdx.x) >> 5;
    int lane = threadIdx.x & 31;
    if (node >= N_NODES) return;

    constexpr int V = DOUT / 64;   // half2 pairs per lane: 2 (128) or 1 (64)

    float2 acc[V];
    float s = g_self[node];
    {
        const __half2* hp = reinterpret_cast<const __half2*>(
            &H[(size_t)node * DOUT + lane * (V * 2)]);
#pragma unroll
        for (int c = 0; c < V; c++) {
            float2 f = __half22float2(hp[c]);
            acc[c].x = s * f.x;
            acc[c].y = s * f.y;
        }
    }

    const int2* __restrict__ ep = g_edges;
    int beg = g_offsets[node];
    int end = g_offsets[node + 1];

    int j = beg;
    for (; j + 4 <= end; j += 4) {
        int2 e0 = ep[j], e1 = ep[j + 1], e2 = ep[j + 2], e3 = ep[j + 3];
        float n0 = __int_as_float(e0.y), n1 = __int_as_float(e1.y);
        float n2 = __int_as_float(e2.y), n3 = __int_as_float(e3.y);
        const __half2* h0 = reinterpret_cast<const __half2*>(
            &H[(size_t)e0.x * DOUT + lane * (V * 2)]);
        const __half2* h1 = reinterpret_cast<const __half2*>(
            &H[(size_t)e1.x * DOUT + lane * (V * 2)]);
        const __half2* h2 = reinterpret_cast<const __half2*>(
            &H[(size_t)e2.x * DOUT + lane * (V * 2)]);
        const __half2* h3 = reinterpret_cast<const __half2*>(
            &H[(size_t)e3.x * DOUT + lane * (V * 2)]);
        if constexpr (V == 2) {
            uint2 r0 = *reinterpret_cast<const uint2*>(h0);
            uint2 r1 = *reinterpret_cast<const uint2*>(h1);
            uint2 r2 = *reinterpret_cast<const uint2*>(h2);
            uint2 r3 = *reinterpret_cast<const uint2*>(h3);
            float2 f;
            f = __half22float2(*reinterpret_cast<__half2*>(&r0.x));
            acc[0].x += n0 * f.x; acc[0].y += n0 * f.y;
            f = __half22float2(*reinterpret_cast<__half2*>(&r0.y));
            acc[1].x += n0 * f.x; acc[1].y += n0 * f.y;
            f = __half22float2(*reinterpret_cast<__half2*>(&r1.x));
            acc[0].x += n1 * f.x; acc[0].y += n1 * f.y;
            f = __half22float2(*reinterpret_cast<__half2*>(&r1.y));
            acc[1].x += n1 * f.x; acc[1].y += n1 * f.y;
            f = __half22float2(*reinterpret_cast<__half2*>(&r2.x));
            acc[0].x += n2 * f.x; acc[0].y += n2 * f.y;
            f = __half22float2(*reinterpret_cast<__half2*>(&r2.y));
            acc[1].x += n2 * f.x; acc[1].y += n2 * f.y;
            f = __half22float2(*reinterpret_cast<__half2*>(&r3.x));
            acc[0].x += n3 * f.x; acc[0].y += n3 * f.y;
            f = __half22float2(*reinterpret_cast<__half2*>(&r3.y));
            acc[1].x += n3 * f.x; acc[1].y += n3 * f.y;
        } else {
            float2 f;
            f = __half22float2(h0[0]); acc[0].x += n0 * f.x; acc[0].y += n0 * f.y;
            f = __half22float2(h1[0]); acc[0].x += n1 * f.x; acc[0].y += n1 * f.y;
            f = __half22float2(h2[0]); acc[0].x += n2 * f.x; acc[0].y += n2 * f.y;
            f = __half22float2(h3[0]); acc[0].x += n3 * f.x; acc[0].y += n3 * f.y;
        }
    }
    for (; j < end; j++) {
        int2 e = ep[j];
        float nm = __int_as_float(e.y);
        const __half2* h = reinterpret_cast<const __half2*>(
            &H[(size_t)e.x * DOUT + lane * (V * 2)]);
#pragma unroll
        for (int c = 0; c < V; c++) {
            float2 f = __half22float2(h[c]);
            acc[c].x += nm * f.x;
            acc[c].y += nm * f.y;
        }
    }

    // bias + relu + store
#pragma unroll
    for (int c = 0; c < V; c++) {
        float2 b = *reinterpret_cast<const float2*>(&bias[lane * (V * 2) + c * 2]);
        acc[c].x += b.x;
        acc[c].y += b.y;
        if (RELU) {
            acc[c].x = fmaxf(acc[c].x, 0.0f);
            acc[c].y = fmaxf(acc[c].y, 0.0f);
        }
    }
    if constexpr (sizeof(TOUT) == 2) {
        __half2* op = reinterpret_cast<__half2*>(
            &reinterpret_cast<__half*>(out)[(size_t)node * DOUT + lane * (V * 2)]);
#pragma unroll
        for (int c = 0; c < V; c++) op[c] = __floats2half2_rn(acc[c].x, acc[c].y);
    } else {
        float* op = &reinterpret_cast<float*>(out)[(size_t)node * DOUT + lane * (V * 2)];
#pragma unroll
        for (int c = 0; c < V; c++)
            *reinterpret_cast<float2*>(&op[c * 2]) = acc[c];
    }
}

// ----------------------------- launch ---------------------------------------
extern "C" void kernel_launch(void* const* d_in, const int* in_sizes, int n_in,
                              void* d_out, int out_size) {
    const float* x  = (const float*)d_in[0];
    const float* ew = (const float*)d_in[1];
    const int*   ei = (const int*)d_in[2];
    const float* W1 = (const float*)d_in[3];
    const float* b1 = (const float*)d_in[4];
    const float* W2 = (const float*)d_in[5];
    const float* b2 = (const float*)d_in[6];
    const float* W3 = (const float*)d_in[7];
    const float* b3 = (const float*)d_in[8];
    const float* W4 = (const float*)d_in[9];
    const float* b4 = (const float*)d_in[10];
    float* out = (float*)d_out;

    __half *bufA, *bufB;
    cudaGetSymbolAddress((void**)&bufA, g_bufA);
    cudaGetSymbolAddress((void**)&bufB, g_bufB);
    uint32_t* wp128;
    uint32_t* wp64;
    cudaGetSymbolAddress((void**)&wp128, g_w128p);
    cudaGetSymbolAddress((void**)&wp64, g_w64p);
    auto W128 = [&](int m, int plane) { return wp128 + ((size_t)m * 2 + plane) * 64 * 136; };
    auto W64  = [&](int plane) { return wp64 + (size_t)plane * 64 * 72; };

    const int NB_N  = (N_NODES + 255) / 256;
    const int NB_E  = (N_EDGES + 255) / 256;
    const int NB_SC = (N_NODES + SCAN_BS - 1) / SCAN_BS;
    const int ROW_BLOCKS = (N_NODES + 63) / 64;           // 1563
    const dim3 GEMM_GRID128(ROW_BLOCKS, 2);
    const dim3 GEMM_GRID64(ROW_BLOCKS, 1);
    const int AGG_BLOCKS  = (N_NODES * 32 + 255) / 256;

    const int SMEM_G = 17408 + 2 * 64 * 72 * 4;           // 54272 (both variants)
    cudaFuncSetAttribute(k_gemm_mma<float, 128>,
                         cudaFuncAttributeMaxDynamicSharedMemorySize, SMEM_G);
    cudaFuncSetAttribute(k_gemm_mma<__half, 128>,
                         cudaFuncAttributeMaxDynamicSharedMemorySize, SMEM_G);
    cudaFuncSetAttribute(k_gemm_mma<__half, 64>,
                         cudaFuncAttributeMaxDynamicSharedMemorySize, SMEM_G);

    // #1..#3: preproc not needed by gemm1 (ncu slot alignment)
    k_init_nodes<<<NB_N, 256>>>();
    k_edge_degree<<<NB_E, 256>>>(ei, ew);
    k_wconv<<<4, 256>>>(W1, W2, W3, W4);
    // #4: gemm layer 1 (captured by ncu -s/-c window)
    k_gemm_mma<float, 128><<<GEMM_GRID128, 256, SMEM_G>>>(x, W128(0, 0), W128(0, 1), bufA);
    // #5..#8: rest of preprocessing
    k_scanA<<<NB_SC, SCAN_BS>>>();
    k_scanB<<<1, 32>>>(NB_SC);
    k_scanC<<<NB_SC, SCAN_BS>>>();
    k_place<<<NB_E, 256>>>(ei, ew);
    // #9..: layers
    k_agg<128, true, __half><<<AGG_BLOCKS, 256>>>(bufA, b1, bufB);

    k_gemm_mma<__half, 128><<<GEMM_GRID128, 256, SMEM_G>>>(bufB, W128(1, 0), W128(1, 1), bufA);
    k_agg<128, true, __half><<<AGG_BLOCKS, 256>>>(bufA, b2, bufB);

    k_gemm_mma<__half, 128><<<GEMM_GRID128, 256, SMEM_G>>>(bufB, W128(2, 0), W128(2, 1), bufA);
    k_agg<128, true, __half><<<AGG_BLOCKS, 256>>>(bufA, b3, bufB);

    k_gemm_mma<__half, 64><<<GEMM_GRID64, 256, SMEM_G>>>(bufB, W64(0), W64(1), bufA);
    k_agg<64, false, float><<<AGG_BLOCKS, 256>>>(bufA, b4, out);
}